// round 1
// baseline (speedup 1.0000x reference)
#include <cuda_runtime.h>

#define NN 20000
#define EE 320000
#define ETOT (EE + NN)
#define C1 256
#define C2 128
#define H1 4
#define NEG 0.2f
#define BN_EPS 1e-5f

// ---------------- scratch (no allocs allowed) ----------------
__device__ __align__(16) float g_h1[NN * C1];      // x@W1
__device__ __align__(16) float g_b1[NN * C1];      // layer1 aggregated / BN+ELU in place
__device__ __align__(16) float g_h2[NN * C2];      // bn1@W2
__device__ __align__(16) float g_b2[NN * C2];      // layer2 aggregated
__device__ __align__(16) float g_as1[NN * H1];
__device__ __align__(16) float g_ad1[NN * H1];
__device__ __align__(16) float g_e1[(size_t)ETOT * H1];
__device__ __align__(16) float g_den1[NN * H1];
__device__ int   g_max1[NN * H1];
__device__ float g_as2[NN], g_ad2[NN];
__device__ float g_e2[ETOT];
__device__ float g_den2[NN];
__device__ int   g_max2[NN];
__device__ int   g_src[ETOT], g_dst[ETOT];
__device__ int   g_cnt[NN], g_cur[NN], g_eord[ETOT];
__device__ int   g_off[NN + 1];
__device__ float g_sum[C1], g_sq[C1];
__device__ int   g_is64;

// ---------------- helpers ----------------
__device__ __forceinline__ int f2ord(float f) {
    int i = __float_as_int(f);
    return i >= 0 ? i : i ^ 0x7FFFFFFF;
}
__device__ __forceinline__ float ord2f(int i) {
    return __int_as_float(i >= 0 ? i : i ^ 0x7FFFFFFF);
}
__device__ __forceinline__ float lrelu(float v) { return v > 0.f ? v : NEG * v; }

// detect int64 vs int32 edge_index: if int64, high words (odd 32-bit words) of
// first 64 elements are all zero (values in [0,20000)).
__global__ void k_detect(const unsigned* __restrict__ p) {
    int all0 = 1;
    for (int i = 0; i < 64; i++) all0 &= (p[2 * i + 1] == 0u);
    g_is64 = all0;
}

// ---------------- SGEMM: C[M,N] = A[M,K] @ B[K,N], row-major ----------------
__device__ __forceinline__ void sgemm_body(const float* __restrict__ A,
                                           const float* __restrict__ B,
                                           float* __restrict__ C,
                                           int M, int N, int K) {
    __shared__ float As[16][64];
    __shared__ float Bs[16][64];
    int tid = threadIdx.x;           // 256 threads
    int tn = tid & 15, tm = tid >> 4;
    int row0 = blockIdx.y * 64, col0 = blockIdx.x * 64;
    float acc[4][4] = {};
    for (int k0 = 0; k0 < K; k0 += 16) {
#pragma unroll
        for (int i = 0; i < 4; i++) {
            int lin = tid + i * 256;        // 0..1023
            int m = lin >> 4, k = lin & 15; // consecutive tid -> consecutive k
            int r = row0 + m;
            As[k][m] = (r < M) ? A[(size_t)r * K + k0 + k] : 0.f;
        }
#pragma unroll
        for (int i = 0; i < 4; i++) {
            int lin = tid + i * 256;
            int k = lin >> 6, n = lin & 63;
            Bs[k][n] = B[(size_t)(k0 + k) * N + col0 + n];
        }
        __syncthreads();
#pragma unroll
        for (int k = 0; k < 16; k++) {
            float ra[4], rb[4];
#pragma unroll
            for (int i = 0; i < 4; i++) ra[i] = As[k][tm * 4 + i];
#pragma unroll
            for (int j = 0; j < 4; j++) rb[j] = Bs[k][tn * 4 + j];
#pragma unroll
            for (int i = 0; i < 4; i++)
#pragma unroll
                for (int j = 0; j < 4; j++) acc[i][j] += ra[i] * rb[j];
        }
        __syncthreads();
    }
#pragma unroll
    for (int i = 0; i < 4; i++) {
        int r = row0 + tm * 4 + i;
        if (r >= M) continue;
#pragma unroll
        for (int j = 0; j < 4; j++)
            C[(size_t)r * N + col0 + tn * 4 + j] = acc[i][j];
    }
}

__global__ void k_gemm1(const float* __restrict__ x, const float* __restrict__ W1) {
    sgemm_body(x, W1, g_h1, NN, C1, 128);
}
__global__ void k_gemm2(const float* __restrict__ W2) {
    sgemm_body(g_b1, W2, g_h2, NN, C2, C1);
}

// ---------------- per-node alpha projections ----------------
__global__ void k_alphas1(const float* __restrict__ attS, const float* __restrict__ attD) {
    int idx = blockIdx.x * blockDim.x + threadIdx.x;
    if (idx < NN) g_cnt[idx] = 0;
    if (idx < C1) { g_sum[idx] = 0.f; g_sq[idx] = 0.f; }
    if (idx >= NN * H1) return;
    int n = idx >> 2, h = idx & 3;
    const float4* hp = (const float4*)(g_h1 + (size_t)n * C1 + h * 64);
    const float4* ap = (const float4*)(attS + h * 64);
    const float4* bp = (const float4*)(attD + h * 64);
    float s = 0.f, d = 0.f;
#pragma unroll
    for (int i = 0; i < 16; i++) {
        float4 hv = hp[i], a = ap[i], b = bp[i];
        s += hv.x * a.x + hv.y * a.y + hv.z * a.z + hv.w * a.w;
        d += hv.x * b.x + hv.y * b.y + hv.z * b.z + hv.w * b.w;
    }
    g_as1[idx] = s;
    g_ad1[idx] = d;
    g_max1[idx] = (int)0x80000000;
    g_den1[idx] = 0.f;
}

__global__ void k_alphas2(const float* __restrict__ attS, const float* __restrict__ attD) {
    int n = blockIdx.x * blockDim.x + threadIdx.x;
    if (n < C1) { g_sum[n] = 0.f; g_sq[n] = 0.f; }
    if (n >= NN) return;
    const float4* hp = (const float4*)(g_h2 + (size_t)n * C2);
    const float4* ap = (const float4*)attS;
    const float4* bp = (const float4*)attD;
    float s = 0.f, d = 0.f;
#pragma unroll
    for (int i = 0; i < 32; i++) {
        float4 hv = hp[i], a = ap[i], b = bp[i];
        s += hv.x * a.x + hv.y * a.y + hv.z * a.z + hv.w * a.w;
        d += hv.x * b.x + hv.y * b.y + hv.z * b.z + hv.w * b.w;
    }
    g_as2[n] = s;
    g_ad2[n] = d;
    g_max2[n] = (int)0x80000000;
    g_den2[n] = 0.f;
}

// ---------------- edge passes, layer 1 ----------------
__global__ void k_pass1_l1(const void* __restrict__ ei) {
    int e = blockIdx.x * blockDim.x + threadIdx.x;
    if (e >= ETOT) return;
    int s, d;
    if (e < EE) {
        if (g_is64) {
            s = (int)((const long long*)ei)[e];
            d = (int)((const long long*)ei)[EE + e];
        } else {
            s = ((const int*)ei)[e];
            d = ((const int*)ei)[EE + e];
        }
    } else {
        s = d = e - EE;
    }
    g_src[e] = s;
    g_dst[e] = d;
    atomicAdd(&g_cnt[d], 1);
    float4 a = *(const float4*)(g_as1 + s * 4);
    float4 b = *(const float4*)(g_ad1 + d * 4);
    float4 v;
    v.x = lrelu(a.x + b.x);
    v.y = lrelu(a.y + b.y);
    v.z = lrelu(a.z + b.z);
    v.w = lrelu(a.w + b.w);
    *(float4*)(g_e1 + (size_t)e * 4) = v;
    atomicMax(&g_max1[d * 4 + 0], f2ord(v.x));
    atomicMax(&g_max1[d * 4 + 1], f2ord(v.y));
    atomicMax(&g_max1[d * 4 + 2], f2ord(v.z));
    atomicMax(&g_max1[d * 4 + 3], f2ord(v.w));
}

// single-block scan of g_cnt -> g_off (inclusive at i+1), g_cur (exclusive)
__global__ void k_scan() {
    __shared__ int sh[1024];
    __shared__ int carry;
    int t = threadIdx.x;
    if (t == 0) { carry = 0; g_off[0] = 0; }
    __syncthreads();
    for (int base = 0; base < NN; base += 1024) {
        int i = base + t;
        int v = (i < NN) ? g_cnt[i] : 0;
        sh[t] = v;
        __syncthreads();
        for (int o = 1; o < 1024; o <<= 1) {
            int add = (t >= o) ? sh[t - o] : 0;
            __syncthreads();
            sh[t] += add;
            __syncthreads();
        }
        if (i < NN) {
            int incl = carry + sh[t];
            g_off[i + 1] = incl;
            g_cur[i] = incl - v;
        }
        __syncthreads();
        if (t == 1023) carry += sh[1023];
        __syncthreads();
    }
}

__global__ void k_scatter() {
    int e = blockIdx.x * blockDim.x + threadIdx.x;
    if (e >= ETOT) return;
    int d = g_dst[e];
    int p = atomicAdd(&g_cur[d], 1);
    g_eord[p] = e;
}

__global__ void k_pass2_l1() {
    int e = blockIdx.x * blockDim.x + threadIdx.x;
    if (e >= ETOT) return;
    int d = g_dst[e];
    float4 v = *(const float4*)(g_e1 + (size_t)e * 4);
    v.x = __expf(v.x - ord2f(g_max1[d * 4 + 0]));
    v.y = __expf(v.y - ord2f(g_max1[d * 4 + 1]));
    v.z = __expf(v.z - ord2f(g_max1[d * 4 + 2]));
    v.w = __expf(v.w - ord2f(g_max1[d * 4 + 3]));
    *(float4*)(g_e1 + (size_t)e * 4) = v;
    atomicAdd(&g_den1[d * 4 + 0], v.x);
    atomicAdd(&g_den1[d * 4 + 1], v.y);
    atomicAdd(&g_den1[d * 4 + 2], v.z);
    atomicAdd(&g_den1[d * 4 + 3], v.w);
}

// CSR aggregation, layer 1: one block (256 thr) per destination, atomic-free
__global__ void k_agg1() {
    int d = blockIdx.x, tid = threadIdx.x;
    int head = tid >> 6;
    int beg = g_off[d], end = g_off[d + 1];
    __shared__ int ssrc[128];
    __shared__ __align__(16) float sal[128 * 4];
    float acc = 0.f;
    for (int base = beg; base < end; base += 128) {
        int cnt = min(128, end - base);
        __syncthreads();
        for (int i = tid; i < cnt; i += 256) {
            int e = g_eord[base + i];
            ssrc[i] = g_src[e];
            *(float4*)(sal + i * 4) = *(const float4*)(g_e1 + (size_t)e * 4);
        }
        __syncthreads();
        int i = 0;
        for (; i + 4 <= cnt; i += 4) {
            float x0 = g_h1[(size_t)ssrc[i] * C1 + tid];
            float x1 = g_h1[(size_t)ssrc[i + 1] * C1 + tid];
            float x2 = g_h1[(size_t)ssrc[i + 2] * C1 + tid];
            float x3 = g_h1[(size_t)ssrc[i + 3] * C1 + tid];
            acc += x0 * sal[i * 4 + head] + x1 * sal[(i + 1) * 4 + head] +
                   x2 * sal[(i + 2) * 4 + head] + x3 * sal[(i + 3) * 4 + head];
        }
        for (; i < cnt; i++)
            acc += g_h1[(size_t)ssrc[i] * C1 + tid] * sal[i * 4 + head];
    }
    float dv = g_den1[d * 4 + head] + 1e-16f;
    g_b1[(size_t)d * C1 + tid] = acc / dv;
}

// ---------------- edge passes, layer 2 (1 head) ----------------
__global__ void k_pass1_l2() {
    int e = blockIdx.x * blockDim.x + threadIdx.x;
    if (e >= ETOT) return;
    int s = g_src[e], d = g_dst[e];
    float v = lrelu(g_as2[s] + g_ad2[d]);
    g_e2[e] = v;
    atomicMax(&g_max2[d], f2ord(v));
}

__global__ void k_pass2_l2() {
    int e = blockIdx.x * blockDim.x + threadIdx.x;
    if (e >= ETOT) return;
    int d = g_dst[e];
    float ex = __expf(g_e2[e] - ord2f(g_max2[d]));
    g_e2[e] = ex;
    atomicAdd(&g_den2[d], ex);
}

__global__ void k_agg2() {
    int d = blockIdx.x, tid = threadIdx.x;  // 128 threads
    int beg = g_off[d], end = g_off[d + 1];
    __shared__ int ssrc[128];
    __shared__ float sal[128];
    float acc = 0.f;
    for (int base = beg; base < end; base += 128) {
        int cnt = min(128, end - base);
        __syncthreads();
        for (int i = tid; i < cnt; i += 128) {
            int e = g_eord[base + i];
            ssrc[i] = g_src[e];
            sal[i] = g_e2[e];
        }
        __syncthreads();
        int i = 0;
        for (; i + 4 <= cnt; i += 4) {
            acc += g_h2[(size_t)ssrc[i] * C2 + tid] * sal[i] +
                   g_h2[(size_t)ssrc[i + 1] * C2 + tid] * sal[i + 1] +
                   g_h2[(size_t)ssrc[i + 2] * C2 + tid] * sal[i + 2] +
                   g_h2[(size_t)ssrc[i + 3] * C2 + tid] * sal[i + 3];
        }
        for (; i < cnt; i++)
            acc += g_h2[(size_t)ssrc[i] * C2 + tid] * sal[i];
    }
    g_b2[(size_t)d * C2 + tid] = acc / (g_den2[d] + 1e-16f);
}

// ---------------- BatchNorm ----------------
__global__ void k_bnred1() {
    int c = threadIdx.x;  // C1 threads
    int rows = (NN + gridDim.x - 1) / gridDim.x;
    int r0 = blockIdx.x * rows, r1 = min(NN, r0 + rows);
    float s = 0.f, q = 0.f;
    for (int r = r0; r < r1; r++) {
        float v = g_b1[(size_t)r * C1 + c];
        s += v;
        q += v * v;
    }
    atomicAdd(&g_sum[c], s);
    atomicAdd(&g_sq[c], q);
}
__global__ void k_bnred2() {
    int c = threadIdx.x;  // C2 threads
    int rows = (NN + gridDim.x - 1) / gridDim.x;
    int r0 = blockIdx.x * rows, r1 = min(NN, r0 + rows);
    float s = 0.f, q = 0.f;
    for (int r = r0; r < r1; r++) {
        float v = g_b2[(size_t)r * C2 + c];
        s += v;
        q += v * v;
    }
    atomicAdd(&g_sum[c], s);
    atomicAdd(&g_sq[c], q);
}

// BN apply (+ELU) in place on g_b1
__global__ void k_bnapply1(const float* __restrict__ gamma, const float* __restrict__ beta) {
    int i = blockIdx.x * blockDim.x + threadIdx.x;
    if (i >= NN * C1) return;
    int c = i & (C1 - 1);
    float mean = g_sum[c] * (1.f / NN);
    float var = g_sq[c] * (1.f / NN) - mean * mean;
    float v = (g_b1[i] - mean) * rsqrtf(var + BN_EPS) * gamma[c] + beta[c];
    g_b1[i] = v > 0.f ? v : expm1f(v);
}
// BN apply to output
__global__ void k_bnapply2(float* __restrict__ out, const float* __restrict__ gamma,
                           const float* __restrict__ beta) {
    int i = blockIdx.x * blockDim.x + threadIdx.x;
    if (i >= NN * C2) return;
    int c = i & (C2 - 1);
    float mean = g_sum[c] * (1.f / NN);
    float var = g_sq[c] * (1.f / NN) - mean * mean;
    out[i] = (g_b2[i] - mean) * rsqrtf(var + BN_EPS) * gamma[c] + beta[c];
}

// ---------------- launch ----------------
extern "C" void kernel_launch(void* const* d_in, const int* in_sizes, int n_in,
                              void* d_out, int out_size) {
    const float* x   = (const float*)d_in[0];
    const void*  ei  = d_in[1];
    const float* W1  = (const float*)d_in[2];
    const float* as1 = (const float*)d_in[3];
    const float* ad1 = (const float*)d_in[4];
    const float* gm1 = (const float*)d_in[6];
    const float* bt1 = (const float*)d_in[7];
    const float* W2  = (const float*)d_in[8];
    const float* as2 = (const float*)d_in[9];
    const float* ad2 = (const float*)d_in[10];
    const float* gm2 = (const float*)d_in[12];
    const float* bt2 = (const float*)d_in[13];
    float* out = (float*)d_out;

    const int EB = (ETOT + 255) / 256;

    k_detect<<<1, 1>>>((const unsigned*)ei);

    // layer 1
    k_gemm1<<<dim3(C1 / 64, (NN + 63) / 64), 256>>>(x, W1);
    k_alphas1<<<(NN * H1 + 255) / 256, 256>>>(as1, ad1);
    k_pass1_l1<<<EB, 256>>>(ei);
    k_scan<<<1, 1024>>>();
    k_scatter<<<EB, 256>>>();
    k_pass2_l1<<<EB, 256>>>();
    k_agg1<<<NN, 256>>>();
    k_bnred1<<<80, C1>>>();
    k_bnapply1<<<(NN * C1 + 255) / 256, 256>>>(gm1, bt1);

    // layer 2
    k_gemm2<<<dim3(C2 / 64, (NN + 63) / 64), 256>>>(W2);
    k_alphas2<<<(NN + 255) / 256, 256>>>(as2, ad2);
    k_pass1_l2<<<EB, 256>>>();
    k_pass2_l2<<<EB, 256>>>();
    k_agg2<<<NN, 128>>>();
    k_bnred2<<<80, C2>>>();
    k_bnapply2<<<(NN * C2 + 255) / 256, 256>>>(out, gm2, bt2);
}